// round 6
// baseline (speedup 1.0000x reference)
#include <cuda_runtime.h>
#include <cuda_bf16.h>
#include <math.h>

#define NN 50000
#define EE 1600000
#define IND 256
#define OUTD 64
#define NH 4
typedef unsigned long long ull;

// ---------------- scratch (static device arrays; zero-initialized) ----------
__device__ float  g_x[NN * OUTD];          // 12.8 MB  x = h@W
__device__ float4 g_el[NN];
__device__ float4 g_er[NN];
__device__ int    g_deg[NN];               // invariant: zero at kernel_launch entry
__device__ int    g_off[NN + 1];
__device__ int    g_cur[NN];
__device__ int    g_dst_s[EE];             // CSR-sorted dst

// ---------------- helpers ----------------------------------------------------
#define L2E  1.4426950408889634f
#define L2E2 0.28853900817779268f   // 0.2 * log2(e)

__device__ __forceinline__ float lrelu_exp(float v)
{
    return exp2f(fmaxf(v, 0.f) * L2E + fminf(v, 0.f) * L2E2);
}
__device__ __forceinline__ float elu1(float v)
{
    return (v > 0.f) ? v : expm1f(v);
}
__device__ __forceinline__ ull dup2(float v)
{
    ull r; asm("mov.b64 %0, {%1, %1};" : "=l"(r) : "f"(v)); return r;
}
union U64 { ull u; float2 f; };

// ---------------- K1: x = h @ W  (pipelined, double-buffered, f32x2) ---------
// 128x64 tile, 256 threads, 8x4 microtile; rows paired into f32x2 lanes.
__global__ void __launch_bounds__(256) k_gemm(const float* __restrict__ h,
                                              const float* __restrict__ W, int N)
{
    __shared__ float  As2[2][32][132];   // k-major, m-contiguous, pad 132
    __shared__ float4 Bs[2][32 * 16];

    const int tid = threadIdx.x;
    const int m0  = blockIdx.x * 128;
    const int tx  = tid & 15;
    const int ty  = tid >> 4;

    // A-load geometry (fixed per thread): 4 fragments
    const int rowA = tid >> 3;           // 0..31  (row  = f>>3 for f=tid+256l -> row = tid>>3 + 32l)
    const int kqA  = tid & 7;            // k-quad
    // B-load geometry: 2 fragments
    const int kkB  = tid >> 4;           // 0..15 (+16 for second)
    const int nqB  = tid & 15;

    float4 pa[4], pb[2];

    auto ldgTile = [&](int k0) {
#pragma unroll
        for (int l = 0; l < 4; l++) {
            int gm = m0 + rowA + 32 * l;
            pa[l] = make_float4(0.f, 0.f, 0.f, 0.f);
            if (gm < N) pa[l] = *(const float4*)(h + (size_t)gm * IND + k0 + kqA * 4);
        }
#pragma unroll
        for (int l = 0; l < 2; l++)
            pb[l] = *(const float4*)(W + (size_t)(k0 + kkB + 16 * l) * OUTD + nqB * 4);
    };
    auto stsTile = [&](int s) {
#pragma unroll
        for (int l = 0; l < 4; l++) {
            int row = rowA + 32 * l;
            As2[s][kqA * 4 + 0][row] = pa[l].x;
            As2[s][kqA * 4 + 1][row] = pa[l].y;
            As2[s][kqA * 4 + 2][row] = pa[l].z;
            As2[s][kqA * 4 + 3][row] = pa[l].w;
        }
#pragma unroll
        for (int l = 0; l < 2; l++)
            Bs[s][(kkB + 16 * l) * 16 + nqB] = pb[l];
    };

    ull acc2[4][4];
#pragma unroll
    for (int r = 0; r < 4; r++)
#pragma unroll
        for (int j = 0; j < 4; j++) acc2[r][j] = 0ull;

    ldgTile(0);
    stsTile(0);
    __syncthreads();

    const int NT = IND / 32;             // 8 tiles
#pragma unroll
    for (int t = 0; t < NT; t++) {
        if (t < NT - 1) ldgTile((t + 1) * 32);    // prefetch next tile into regs

        const int s = t & 1;
#pragma unroll
        for (int k = 0; k < 32; k++) {
            const ull* ap = (const ull*)&As2[s][k][ty * 8];
            ull a[4] = {ap[0], ap[1], ap[2], ap[3]};
            float4 bv = Bs[s][k * 16 + tx];
            ull b0 = dup2(bv.x), b1 = dup2(bv.y), b2 = dup2(bv.z), b3 = dup2(bv.w);
#pragma unroll
            for (int r = 0; r < 4; r++) {
                asm("fma.rn.f32x2 %0, %1, %2, %0;" : "+l"(acc2[r][0]) : "l"(a[r]), "l"(b0));
                asm("fma.rn.f32x2 %0, %1, %2, %0;" : "+l"(acc2[r][1]) : "l"(a[r]), "l"(b1));
                asm("fma.rn.f32x2 %0, %1, %2, %0;" : "+l"(acc2[r][2]) : "l"(a[r]), "l"(b2));
                asm("fma.rn.f32x2 %0, %1, %2, %0;" : "+l"(acc2[r][3]) : "l"(a[r]), "l"(b3));
            }
        }
        if (t < NT - 1) stsTile((t + 1) & 1);     // write other buffer
        __syncthreads();
    }

#pragma unroll
    for (int r = 0; r < 4; r++) {
        int gm0 = m0 + ty * 8 + 2 * r;
        U64 t0, t1, t2, t3;
        t0.u = acc2[r][0]; t1.u = acc2[r][1]; t2.u = acc2[r][2]; t3.u = acc2[r][3];
        if (gm0 < N)
            *(float4*)(g_x + (size_t)gm0 * OUTD + tx * 4) =
                make_float4(t0.f.x, t1.f.x, t2.f.x, t3.f.x);
        if (gm0 + 1 < N)
            *(float4*)(g_x + (size_t)(gm0 + 1) * OUTD + tx * 4) =
                make_float4(t0.f.y, t1.f.y, t2.f.y, t3.f.y);
    }
}

// ---------------- K2: degree histogram ---------------------------------------
__global__ void k_deg(const int* __restrict__ ei, int E)
{
    int stride = gridDim.x * blockDim.x;
    const int4* e4 = (const int4*)ei;
    int E4 = E >> 2;
    for (int i = blockIdx.x * blockDim.x + threadIdx.x; i < E4; i += stride) {
        int4 v = e4[i];
        atomicAdd(&g_deg[v.x], 1);
        atomicAdd(&g_deg[v.y], 1);
        atomicAdd(&g_deg[v.z], 1);
        atomicAdd(&g_deg[v.w], 1);
    }
    for (int e = (E & ~3) + blockIdx.x * blockDim.x + threadIdx.x; e < E; e += stride)
        atomicAdd(&g_deg[ei[e]], 1);
}

// ---------------- K3: exclusive scan + deg re-zero ---------------------------
__global__ void k_scan(int N)
{
    __shared__ int sm[1024];
    const int t  = threadIdx.x;
    const int CH = (N + 1023) / 1024;
    int beg = t * CH;
    int end = beg + CH; if (end > N) end = N;

    int s = 0;
    for (int i = beg; i < end; i++) s += g_deg[i];
    sm[t] = s;
    __syncthreads();
#pragma unroll
    for (int o = 1; o < 1024; o <<= 1) {
        int v = (t >= o) ? sm[t - o] : 0;
        __syncthreads();
        sm[t] += v;
        __syncthreads();
    }
    int run = sm[t] - s;
    for (int i = beg; i < end; i++) {
        int dv = g_deg[i];
        g_off[i] = run;
        g_cur[i] = run;
        g_deg[i] = 0;
        run += dv;
    }
    if (t == 1023) g_off[N] = sm[1023];
}

// ---------------- K4: CSR scatter (dst only), 4 edges/thread -----------------
__global__ void k_scatter(const int* __restrict__ ei, int E)
{
    int i = blockIdx.x * blockDim.x + threadIdx.x;
    int e = i * 4;
    if (((E & 3) == 0) && (e + 4 <= E)) {
        int4 s4 = *(const int4*)(ei + e);
        int4 d4 = *(const int4*)(ei + E + e);
        g_dst_s[atomicAdd(&g_cur[s4.x], 1)] = d4.x;
        g_dst_s[atomicAdd(&g_cur[s4.y], 1)] = d4.y;
        g_dst_s[atomicAdd(&g_cur[s4.z], 1)] = d4.z;
        g_dst_s[atomicAdd(&g_cur[s4.w], 1)] = d4.w;
    } else {
        for (int q = e; q < E && q < e + 4; q++) {
            int s = ei[q];
            int d = ei[E + q];
            g_dst_s[atomicAdd(&g_cur[s], 1)] = d;
        }
    }
}

// ---------------- K5: el/er projections (warp per node) ----------------------
__global__ void k_elr(const float* __restrict__ Wl, const float* __restrict__ Wr, int N)
{
    int warp = (blockIdx.x * blockDim.x + threadIdx.x) >> 5;
    int lane = threadIdx.x & 31;
    if (warp >= N) return;

    const float* xr = g_x + (size_t)warp * OUTD;
    float x0 = xr[lane];
    float x1 = xr[lane + 32];

    float s[8];
#pragma unroll
    for (int hd = 0; hd < NH; hd++) {
        s[hd]     = x0 * __ldg(Wl + hd * OUTD + lane) + x1 * __ldg(Wl + hd * OUTD + lane + 32);
        s[4 + hd] = x0 * __ldg(Wr + hd * OUTD + lane) + x1 * __ldg(Wr + hd * OUTD + lane + 32);
    }
#pragma unroll
    for (int o = 16; o > 0; o >>= 1) {
#pragma unroll
        for (int j = 0; j < 8; j++) s[j] += __shfl_xor_sync(0xffffffffu, s[j], o);
    }
    if (lane == 0) {
        g_el[warp] = make_float4(s[0], s[1], s[2], s[3]);
        g_er[warp] = make_float4(s[4], s[5], s[6], s[7]);
    }
}

// ---------------- K6: per-node aggregation -----------------------------------
__global__ void __launch_bounds__(128) k_agg(const float* __restrict__ b,
                                             float* __restrict__ out, int N)
{
    __shared__ int    s_off[2][4][32];
    __shared__ float4 s_e[2][4][32][2];

    const int w    = threadIdx.x >> 5;
    const int lane = threadIdx.x & 31;
    const int node = blockIdx.x * 4 + w;
    if (node >= N) return;

    const int s0 = g_off[node];
    const int s1 = g_off[node + 1];
    const float4 el = g_el[node];

    ull a0 = 0ull, a1 = 0ull, a2 = 0ull, a3 = 0ull;
    float e0 = 0.f, e1 = 0.f, e2 = 0.f, e3 = 0.f;

    const float* xl = g_x + lane * 2;

    auto stage = [&](int buf, int c, int n) {
        if (lane < n) {
            int d = g_dst_s[c + lane];
            float4 er = g_er[d];
            float ex = lrelu_exp(el.x + er.x);
            float ey = lrelu_exp(el.y + er.y);
            float ez = lrelu_exp(el.z + er.z);
            float ew = lrelu_exp(el.w + er.w);
            e0 += ex; e1 += ey; e2 += ez; e3 += ew;
            s_off[buf][w][lane]  = d * OUTD;
            s_e[buf][w][lane][0] = make_float4(ex, ex, ey, ey);
            s_e[buf][w][lane][1] = make_float4(ez, ez, ew, ew);
        }
    };

    auto consume32 = [&](int buf) {
#pragma unroll
        for (int g = 0; g < 8; g++) {
            int oo[4]; ull xx[4]; ulonglong2 pa[4], pb[4];
#pragma unroll
            for (int q = 0; q < 4; q++) oo[q] = s_off[buf][w][g * 4 + q];
#pragma unroll
            for (int q = 0; q < 4; q++) xx[q] = *(const ull*)(xl + oo[q]);
#pragma unroll
            for (int q = 0; q < 4; q++) {
                pa[q] = *(const ulonglong2*)&s_e[buf][w][g * 4 + q][0];
                pb[q] = *(const ulonglong2*)&s_e[buf][w][g * 4 + q][1];
            }
#pragma unroll
            for (int q = 0; q < 4; q++) {
                asm("fma.rn.f32x2 %0, %1, %2, %0;" : "+l"(a0) : "l"(pa[q].x), "l"(xx[q]));
                asm("fma.rn.f32x2 %0, %1, %2, %0;" : "+l"(a1) : "l"(pa[q].y), "l"(xx[q]));
                asm("fma.rn.f32x2 %0, %1, %2, %0;" : "+l"(a2) : "l"(pb[q].x), "l"(xx[q]));
                asm("fma.rn.f32x2 %0, %1, %2, %0;" : "+l"(a3) : "l"(pb[q].y), "l"(xx[q]));
            }
        }
    };

    auto consumeTail = [&](int buf, int n) {
        for (int j = 0; j < n; j++) {
            int off = s_off[buf][w][j];
            ulonglong2 p0 = *(const ulonglong2*)&s_e[buf][w][j][0];
            ulonglong2 p1 = *(const ulonglong2*)&s_e[buf][w][j][1];
            ull xv = *(const ull*)(xl + off);
            asm("fma.rn.f32x2 %0, %1, %2, %0;" : "+l"(a0) : "l"(p0.x), "l"(xv));
            asm("fma.rn.f32x2 %0, %1, %2, %0;" : "+l"(a1) : "l"(p0.y), "l"(xv));
            asm("fma.rn.f32x2 %0, %1, %2, %0;" : "+l"(a2) : "l"(p1.x), "l"(xv));
            asm("fma.rn.f32x2 %0, %1, %2, %0;" : "+l"(a3) : "l"(p1.y), "l"(xv));
        }
    };

    int c = s0;
    int buf = 0;
    int n0 = s1 - c; if (n0 > 32) n0 = 32;
    stage(0, c, n0);
    __syncwarp();

    while (c + 32 < s1) {
        int cn = c + 32;
        int nn = s1 - cn; if (nn > 32) nn = 32;
        stage(buf ^ 1, cn, nn);
        consume32(buf);
        __syncwarp();
        buf ^= 1;
        c = cn;
    }
    {
        int n = s1 - c;
        if (n == 32) consume32(buf);
        else if (n > 0) consumeTail(buf, n);
    }

#pragma unroll
    for (int o = 16; o > 0; o >>= 1) {
        e0 += __shfl_xor_sync(0xffffffffu, e0, o);
        e1 += __shfl_xor_sync(0xffffffffu, e1, o);
        e2 += __shfl_xor_sync(0xffffffffu, e2, o);
        e3 += __shfl_xor_sync(0xffffffffu, e3, o);
    }

    float i0 = 1.f / fmaxf(e0, 1e-12f);
    float i1 = 1.f / fmaxf(e1, 1e-12f);
    float i2 = 1.f / fmaxf(e2, 1e-12f);
    float i3 = 1.f / fmaxf(e3, 1e-12f);

    float2 bb = *(const float2*)(b + lane * 2);

    U64 A0, A1, A2, A3;
    A0.u = a0; A1.u = a1; A2.u = a2; A3.u = a3;

    float* o = out + (size_t)node * (NH * OUTD) + lane * 2;
    float2 r;
    r.x = elu1(A0.f.x * i0 + bb.x); r.y = elu1(A0.f.y * i0 + bb.y);
    *(float2*)(o + 0 * OUTD) = r;
    r.x = elu1(A1.f.x * i1 + bb.x); r.y = elu1(A1.f.y * i1 + bb.y);
    *(float2*)(o + 1 * OUTD) = r;
    r.x = elu1(A2.f.x * i2 + bb.x); r.y = elu1(A2.f.y * i2 + bb.y);
    *(float2*)(o + 2 * OUTD) = r;
    r.x = elu1(A3.f.x * i3 + bb.x); r.y = elu1(A3.f.y * i3 + bb.y);
    *(float2*)(o + 3 * OUTD) = r;
}

// ---------------- launch: fork-join two-stream graph --------------------------
extern "C" void kernel_launch(void* const* d_in, const int* in_sizes, int n_in,
                              void* d_out, int out_size)
{
    const float* h  = (const float*)d_in[0];   // [N, 256]
    const float* W  = (const float*)d_in[1];   // [256, 64]
    const float* Wl = (const float*)d_in[2];   // [4, 64]
    const float* Wr = (const float*)d_in[3];   // [4, 64]
    const float* b  = (const float*)d_in[4];   // [64]
    const int*   ei = (const int*)d_in[5];     // [2, E]
    float* out = (float*)d_out;

    int N = in_sizes[0] / IND;
    int E = in_sizes[5] / 2;

    static cudaStream_t s1 = nullptr;
    static cudaEvent_t  evFork = nullptr, evJoin = nullptr;
    if (s1 == nullptr) {
        cudaStreamCreateWithFlags(&s1, cudaStreamNonBlocking);
        cudaEventCreateWithFlags(&evFork, cudaEventDisableTiming);
        cudaEventCreateWithFlags(&evJoin, cudaEventDisableTiming);
    }

    // fork: s1 handles the CSR-build chain (independent of the GEMM)
    cudaEventRecord(evFork, 0);
    cudaStreamWaitEvent(s1, evFork, 0);

    k_deg<<<512, 256, 0, s1>>>(ei, E);
    k_scan<<<1, 1024, 0, s1>>>(N);
    int SB = ((E + 3) / 4 + 255) / 256;
    k_scatter<<<SB, 256, 0, s1>>>(ei, E);
    cudaEventRecord(evJoin, s1);

    // main stream: gemm -> elr
    k_gemm<<<(N + 127) / 128, 256>>>(h, W, N);
    k_elr<<<(N + 7) / 8, 256>>>(Wl, Wr, N);

    // join: agg needs CSR (s1) + el/er (main)
    cudaStreamWaitEvent(0, evJoin, 0);
    k_agg<<<(N + 3) / 4, 128>>>(b, out, N);
}

// round 7
// speedup vs baseline: 1.2074x; 1.2074x over previous
#include <cuda_runtime.h>
#include <cuda_bf16.h>
#include <math.h>

#define NN 50000
#define EE 1600000
#define IND 256
#define OUTD 64
#define NH 4
typedef unsigned long long ull;

// ---------------- scratch (static device arrays; zero-initialized) ----------
__device__ float  g_x[NN * OUTD];          // 12.8 MB  x = h@W
__device__ float4 g_el[NN];
__device__ float4 g_er[NN];
__device__ int    g_deg[NN];               // invariant: zero at kernel_launch entry
__device__ int    g_off[NN + 1];
__device__ int    g_cur[NN];
__device__ int    g_dst_s[EE];             // CSR-sorted dst

// ---------------- helpers ----------------------------------------------------
#define L2E 1.4426950408889634f

__device__ __forceinline__ float lrelu_exp(float v)
{
    // leaky_relu(v,0.2) == fmaxf(v, 0.2*v)  (0.2v > v iff v < 0)
    return exp2f(fmaxf(v, 0.2f * v) * L2E);
}
__device__ __forceinline__ float elu1(float v)
{
    return (v > 0.f) ? v : expm1f(v);
}
__device__ __forceinline__ ull dup2(float v)
{
    ull r; asm("mov.b64 %0, {%1, %1};" : "=l"(r) : "f"(v)); return r;
}
union U64 { ull u; float2 f; };

// ---------------- K1: x = h @ W  (round-5 proven version) --------------------
__global__ void k_gemm(const float* __restrict__ h, const float* __restrict__ W, int N)
{
    __shared__ float  As2[32][132];     // k-major, m-contiguous, pad 132
    __shared__ float4 Bs[32 * 16];

    const int tid = threadIdx.x;
    const int m0  = blockIdx.x * 128;
    const int tx  = tid & 15;
    const int ty  = tid >> 4;

    ull acc2[4][4];
#pragma unroll
    for (int r = 0; r < 4; r++)
#pragma unroll
        for (int j = 0; j < 4; j++) acc2[r][j] = 0ull;

    for (int k0 = 0; k0 < IND; k0 += 32) {
#pragma unroll
        for (int l = 0; l < 4; l++) {
            int f   = tid + 256 * l;
            int row = f >> 3;
            int kq  = f & 7;
            int gm  = m0 + row;
            float4 v = make_float4(0.f, 0.f, 0.f, 0.f);
            if (gm < N) v = *(const float4*)(h + (size_t)gm * IND + k0 + kq * 4);
            As2[kq * 4 + 0][row] = v.x;
            As2[kq * 4 + 1][row] = v.y;
            As2[kq * 4 + 2][row] = v.z;
            As2[kq * 4 + 3][row] = v.w;
        }
#pragma unroll
        for (int l = 0; l < 2; l++) {
            int f  = tid + 256 * l;
            int kk = f >> 4;
            int nq = f & 15;
            Bs[kk * 16 + nq] = *(const float4*)(W + (size_t)(k0 + kk) * OUTD + nq * 4);
        }
        __syncthreads();

#pragma unroll
        for (int k = 0; k < 32; k++) {
            const ull* ap = (const ull*)&As2[k][ty * 8];
            ull a[4] = {ap[0], ap[1], ap[2], ap[3]};
            float4 bv = Bs[k * 16 + tx];
            ull b0 = dup2(bv.x), b1 = dup2(bv.y), b2 = dup2(bv.z), b3 = dup2(bv.w);
#pragma unroll
            for (int r = 0; r < 4; r++) {
                asm("fma.rn.f32x2 %0, %1, %2, %0;" : "+l"(acc2[r][0]) : "l"(a[r]), "l"(b0));
                asm("fma.rn.f32x2 %0, %1, %2, %0;" : "+l"(acc2[r][1]) : "l"(a[r]), "l"(b1));
                asm("fma.rn.f32x2 %0, %1, %2, %0;" : "+l"(acc2[r][2]) : "l"(a[r]), "l"(b2));
                asm("fma.rn.f32x2 %0, %1, %2, %0;" : "+l"(acc2[r][3]) : "l"(a[r]), "l"(b3));
            }
        }
        __syncthreads();
    }

#pragma unroll
    for (int r = 0; r < 4; r++) {
        int gm0 = m0 + ty * 8 + 2 * r;
        U64 t0, t1, t2, t3;
        t0.u = acc2[r][0]; t1.u = acc2[r][1]; t2.u = acc2[r][2]; t3.u = acc2[r][3];
        if (gm0 < N)
            *(float4*)(g_x + (size_t)gm0 * OUTD + tx * 4) =
                make_float4(t0.f.x, t1.f.x, t2.f.x, t3.f.x);
        if (gm0 + 1 < N)
            *(float4*)(g_x + (size_t)(gm0 + 1) * OUTD + tx * 4) =
                make_float4(t0.f.y, t1.f.y, t2.f.y, t3.f.y);
    }
}

// ---------------- K2: degree histogram ---------------------------------------
__global__ void k_deg(const int* __restrict__ ei, int E)
{
    int stride = gridDim.x * blockDim.x;
    const int4* e4 = (const int4*)ei;
    int E4 = E >> 2;
    for (int i = blockIdx.x * blockDim.x + threadIdx.x; i < E4; i += stride) {
        int4 v = e4[i];
        atomicAdd(&g_deg[v.x], 1);
        atomicAdd(&g_deg[v.y], 1);
        atomicAdd(&g_deg[v.z], 1);
        atomicAdd(&g_deg[v.w], 1);
    }
    for (int e = (E & ~3) + blockIdx.x * blockDim.x + threadIdx.x; e < E; e += stride)
        atomicAdd(&g_deg[ei[e]], 1);
}

// ---------------- K3: exclusive scan + deg re-zero ---------------------------
__global__ void k_scan(int N)
{
    __shared__ int sm[1024];
    const int t  = threadIdx.x;
    const int CH = (N + 1023) / 1024;
    int beg = t * CH;
    int end = beg + CH; if (end > N) end = N;

    int s = 0;
    for (int i = beg; i < end; i++) s += g_deg[i];
    sm[t] = s;
    __syncthreads();
#pragma unroll
    for (int o = 1; o < 1024; o <<= 1) {
        int v = (t >= o) ? sm[t - o] : 0;
        __syncthreads();
        sm[t] += v;
        __syncthreads();
    }
    int run = sm[t] - s;
    for (int i = beg; i < end; i++) {
        int dv = g_deg[i];
        g_off[i] = run;
        g_cur[i] = run;
        g_deg[i] = 0;
        run += dv;
    }
    if (t == 1023) g_off[N] = sm[1023];
}

// ---------------- K4: CSR scatter (dst only), 4 edges/thread -----------------
__global__ void k_scatter(const int* __restrict__ ei, int E)
{
    int i = blockIdx.x * blockDim.x + threadIdx.x;
    int e = i * 4;
    if (((E & 3) == 0) && (e + 4 <= E)) {
        int4 s4 = *(const int4*)(ei + e);
        int4 d4 = *(const int4*)(ei + E + e);
        g_dst_s[atomicAdd(&g_cur[s4.x], 1)] = d4.x;
        g_dst_s[atomicAdd(&g_cur[s4.y], 1)] = d4.y;
        g_dst_s[atomicAdd(&g_cur[s4.z], 1)] = d4.z;
        g_dst_s[atomicAdd(&g_cur[s4.w], 1)] = d4.w;
    } else {
        for (int q = e; q < E && q < e + 4; q++) {
            int s = ei[q];
            int d = ei[E + q];
            g_dst_s[atomicAdd(&g_cur[s], 1)] = d;
        }
    }
}

// ---------------- K5: el/er projections (warp per node) ----------------------
__global__ void k_elr(const float* __restrict__ Wl, const float* __restrict__ Wr, int N)
{
    int warp = (blockIdx.x * blockDim.x + threadIdx.x) >> 5;
    int lane = threadIdx.x & 31;
    if (warp >= N) return;

    const float* xr = g_x + (size_t)warp * OUTD;
    float x0 = xr[lane];
    float x1 = xr[lane + 32];

    float s[8];
#pragma unroll
    for (int hd = 0; hd < NH; hd++) {
        s[hd]     = x0 * __ldg(Wl + hd * OUTD + lane) + x1 * __ldg(Wl + hd * OUTD + lane + 32);
        s[4 + hd] = x0 * __ldg(Wr + hd * OUTD + lane) + x1 * __ldg(Wr + hd * OUTD + lane + 32);
    }
#pragma unroll
    for (int o = 16; o > 0; o >>= 1) {
#pragma unroll
        for (int j = 0; j < 8; j++) s[j] += __shfl_xor_sync(0xffffffffu, s[j], o);
    }
    if (lane == 0) {
        g_el[warp] = make_float4(s[0], s[1], s[2], s[3]);
        g_er[warp] = make_float4(s[4], s[5], s[6], s[7]);
    }
}

// ---------------- K6: per-node aggregation (pipelined consume) ---------------
__global__ void __launch_bounds__(128) k_agg(const float* __restrict__ b,
                                             float* __restrict__ out, int N)
{
    __shared__ int    s_off[2][4][32];
    __shared__ float4 s_e[2][4][32][2];

    const int w    = threadIdx.x >> 5;
    const int lane = threadIdx.x & 31;
    const int node = blockIdx.x * 4 + w;
    if (node >= N) return;

    const int s0 = g_off[node];
    const int s1 = g_off[node + 1];
    const float4 el = g_el[node];

    ull a0 = 0ull, a1 = 0ull, a2 = 0ull, a3 = 0ull;
    float e0 = 0.f, e1 = 0.f, e2 = 0.f, e3 = 0.f;

    const float* xl = g_x + lane * 2;

    auto stage = [&](int buf, int c, int n) {
        if (lane < n) {
            int d = g_dst_s[c + lane];
            float4 er = g_er[d];
            float ex = lrelu_exp(el.x + er.x);
            float ey = lrelu_exp(el.y + er.y);
            float ez = lrelu_exp(el.z + er.z);
            float ew = lrelu_exp(el.w + er.w);
            e0 += ex; e1 += ey; e2 += ez; e3 += ew;
            s_off[buf][w][lane]  = d * OUTD;
            s_e[buf][w][lane][0] = make_float4(ex, ex, ey, ey);
            s_e[buf][w][lane][1] = make_float4(ez, ez, ew, ew);
        }
    };

    // pipelined full-chunk consume: group g+1's gathers issued before group g's FMAs
    auto consume32 = [&](int buf) {
        int oo0[4], oo1[4]; ull xx0[4], xx1[4];
#pragma unroll
        for (int q = 0; q < 4; q++) oo0[q] = s_off[buf][w][q];
#pragma unroll
        for (int q = 0; q < 4; q++) xx0[q] = *(const ull*)(xl + oo0[q]);
#pragma unroll
        for (int g = 0; g < 8; g++) {
            if (g < 7) {
#pragma unroll
                for (int q = 0; q < 4; q++) oo1[q] = s_off[buf][w][(g + 1) * 4 + q];
#pragma unroll
                for (int q = 0; q < 4; q++) xx1[q] = *(const ull*)(xl + oo1[q]);
            }
            ulonglong2 pa[4], pb[4];
#pragma unroll
            for (int q = 0; q < 4; q++) {
                pa[q] = *(const ulonglong2*)&s_e[buf][w][g * 4 + q][0];
                pb[q] = *(const ulonglong2*)&s_e[buf][w][g * 4 + q][1];
            }
#pragma unroll
            for (int q = 0; q < 4; q++) {
                asm("fma.rn.f32x2 %0, %1, %2, %0;" : "+l"(a0) : "l"(pa[q].x), "l"(xx0[q]));
                asm("fma.rn.f32x2 %0, %1, %2, %0;" : "+l"(a1) : "l"(pa[q].y), "l"(xx0[q]));
                asm("fma.rn.f32x2 %0, %1, %2, %0;" : "+l"(a2) : "l"(pb[q].x), "l"(xx0[q]));
                asm("fma.rn.f32x2 %0, %1, %2, %0;" : "+l"(a3) : "l"(pb[q].y), "l"(xx0[q]));
            }
#pragma unroll
            for (int q = 0; q < 4; q++) { xx0[q] = xx1[q]; oo0[q] = oo1[q]; }
        }
    };

    auto consumeTail = [&](int buf, int n) {
        for (int j = 0; j < n; j++) {
            int off = s_off[buf][w][j];
            ulonglong2 p0 = *(const ulonglong2*)&s_e[buf][w][j][0];
            ulonglong2 p1 = *(const ulonglong2*)&s_e[buf][w][j][1];
            ull xv = *(const ull*)(xl + off);
            asm("fma.rn.f32x2 %0, %1, %2, %0;" : "+l"(a0) : "l"(p0.x), "l"(xv));
            asm("fma.rn.f32x2 %0, %1, %2, %0;" : "+l"(a1) : "l"(p0.y), "l"(xv));
            asm("fma.rn.f32x2 %0, %1, %2, %0;" : "+l"(a2) : "l"(p1.x), "l"(xv));
            asm("fma.rn.f32x2 %0, %1, %2, %0;" : "+l"(a3) : "l"(p1.y), "l"(xv));
        }
    };

    int c = s0;
    int buf = 0;
    int n0 = s1 - c; if (n0 > 32) n0 = 32;
    stage(0, c, n0);
    __syncwarp();

    while (c + 32 < s1) {
        int cn = c + 32;
        int nn = s1 - cn; if (nn > 32) nn = 32;
        stage(buf ^ 1, cn, nn);
        consume32(buf);
        __syncwarp();
        buf ^= 1;
        c = cn;
    }
    {
        int n = s1 - c;
        if (n == 32) consume32(buf);
        else if (n > 0) consumeTail(buf, n);
    }

#pragma unroll
    for (int o = 16; o > 0; o >>= 1) {
        e0 += __shfl_xor_sync(0xffffffffu, e0, o);
        e1 += __shfl_xor_sync(0xffffffffu, e1, o);
        e2 += __shfl_xor_sync(0xffffffffu, e2, o);
        e3 += __shfl_xor_sync(0xffffffffu, e3, o);
    }

    float i0 = 1.f / fmaxf(e0, 1e-12f);
    float i1 = 1.f / fmaxf(e1, 1e-12f);
    float i2 = 1.f / fmaxf(e2, 1e-12f);
    float i3 = 1.f / fmaxf(e3, 1e-12f);

    float2 bb = *(const float2*)(b + lane * 2);

    U64 A0, A1, A2, A3;
    A0.u = a0; A1.u = a1; A2.u = a2; A3.u = a3;

    float* o = out + (size_t)node * (NH * OUTD) + lane * 2;
    float2 r;
    r.x = elu1(A0.f.x * i0 + bb.x); r.y = elu1(A0.f.y * i0 + bb.y);
    *(float2*)(o + 0 * OUTD) = r;
    r.x = elu1(A1.f.x * i1 + bb.x); r.y = elu1(A1.f.y * i1 + bb.y);
    *(float2*)(o + 1 * OUTD) = r;
    r.x = elu1(A2.f.x * i2 + bb.x); r.y = elu1(A2.f.y * i2 + bb.y);
    *(float2*)(o + 2 * OUTD) = r;
    r.x = elu1(A3.f.x * i3 + bb.x); r.y = elu1(A3.f.y * i3 + bb.y);
    *(float2*)(o + 3 * OUTD) = r;
}

// ---------------- launch: fork-join two-stream graph --------------------------
extern "C" void kernel_launch(void* const* d_in, const int* in_sizes, int n_in,
                              void* d_out, int out_size)
{
    const float* h  = (const float*)d_in[0];   // [N, 256]
    const float* W  = (const float*)d_in[1];   // [256, 64]
    const float* Wl = (const float*)d_in[2];   // [4, 64]
    const float* Wr = (const float*)d_in[3];   // [4, 64]
    const float* b  = (const float*)d_in[4];   // [64]
    const int*   ei = (const int*)d_in[5];     // [2, E]
    float* out = (float*)d_out;

    int N = in_sizes[0] / IND;
    int E = in_sizes[5] / 2;

    static cudaStream_t s1 = nullptr;
    static cudaEvent_t  evFork = nullptr, evJoin = nullptr;
    if (s1 == nullptr) {
        cudaStreamCreateWithFlags(&s1, cudaStreamNonBlocking);
        cudaEventCreateWithFlags(&evFork, cudaEventDisableTiming);
        cudaEventCreateWithFlags(&evJoin, cudaEventDisableTiming);
    }

    // fork: s1 handles the CSR-build chain (independent of the GEMM)
    cudaEventRecord(evFork, 0);
    cudaStreamWaitEvent(s1, evFork, 0);

    k_deg<<<512, 256, 0, s1>>>(ei, E);
    k_scan<<<1, 1024, 0, s1>>>(N);
    int SB = ((E + 3) / 4 + 255) / 256;
    k_scatter<<<SB, 256, 0, s1>>>(ei, E);
    cudaEventRecord(evJoin, s1);

    // main stream: gemm -> elr
    k_gemm<<<(N + 127) / 128, 256>>>(h, W, N);
    k_elr<<<(N + 7) / 8, 256>>>(Wl, Wr, N);

    // join: agg needs CSR (s1) + el/er (main)
    cudaStreamWaitEvent(0, evJoin, 0);
    k_agg<<<(N + 3) / 4, 128>>>(b, out, N);
}